// round 4
// baseline (speedup 1.0000x reference)
#include <cuda_runtime.h>
#include <cstdint>

// Problem constants (fixed by the dataset):
//   N = 50000 nodes, C = 128 channels, E = 400000 edges,
//   T = 12 edge types, P = 16 (4x4 restriction map)
// Y layout per node: [half(src=0/dst=1)][t][p]  -> 2*12*16 = 384 cols
#define NMAX   50000
#define CDIM   128
#define NCOLS  384

// Scratch (allocation-free rule: __device__ globals)
__device__ float g_B[CDIM * NCOLS];                 // 196 KB, tf32-rounded weights
__device__ float g_Y[(size_t)NMAX * NCOLS];         // 76.8 MB, per-node partials
__device__ int   g_idx64;                           // 1 if indices are int64

__device__ __forceinline__ uint32_t f2tf32(float x) {
    uint32_t u;
    asm("cvt.rna.tf32.f32 %0, %1;" : "=r"(u) : "f"(x));
    return u;
}

// ---------------------------------------------------------------------------
// Kernel 0: detect index dtype. edge_types values are 0..11; if stored as
// int64 (little-endian), every odd int32 word is 0. Probability of a false
// int64 verdict on genuine int32 data: (1/12)^256 ~ 0.
// ---------------------------------------------------------------------------
__global__ void detect_kernel(const int* __restrict__ et32) {
    int v = et32[2 * threadIdx.x + 1];
    int any_nonzero = __syncthreads_or(v != 0);
    if (threadIdx.x == 0) g_idx64 = any_nonzero ? 0 : 1;
}

// ---------------------------------------------------------------------------
// Kernel 1: rearrange W [T,2C,P] -> B [C, 384] with col = half*192 + t*16 + p
// and pre-round to tf32 (rna).
// ---------------------------------------------------------------------------
__global__ void prep_B_kernel(const float* __restrict__ W) {
    int i = blockIdx.x * blockDim.x + threadIdx.x;
    if (i >= CDIM * NCOLS) return;
    int c    = i / NCOLS;
    int col  = i - c * NCOLS;
    int half = col / 192;
    int rem  = col - half * 192;
    int t    = rem >> 4;
    int p    = rem & 15;
    // W[t][half*128 + c][p]
    float w = W[((size_t)t * 256 + half * 128 + c) * 16 + p];
    g_B[i] = __uint_as_float(f2tf32(w));
}

// ---------------------------------------------------------------------------
// Kernel 2: Y[M,384] = tf32(X[M,128]) @ g_B[128,384]
// CTA tile 128x128, K chunked in 4 steps of 32 (static smem, 35.8 KB, no
// opt-in attribute needed). 256 threads = 8 warps in 4(M) x 2(N); warp tile
// 32x64 via mma.m16n8k8.tf32.
// Smem strides: As 36 (bank map 4*grp+tig, bijective), Bs 136 (8*tig+grp).
// ---------------------------------------------------------------------------
#define KC        32
#define AS_STRIDE 36
#define BS_STRIDE 136

__global__ void __launch_bounds__(256, 2)
gemm_kernel(const float* __restrict__ X, int M) {
    __shared__ float As[128 * AS_STRIDE];  // [128][36]   18.0 KB
    __shared__ float Bs[KC * BS_STRIDE];   // [32][136]   17.4 KB

    const int m0  = blockIdx.x * 128;
    const int n0  = blockIdx.y * 128;
    const int tid = threadIdx.x;

    const int warp = tid >> 5;
    const int lane = tid & 31;
    const int wm   = warp >> 1;   // 0..3
    const int wn   = warp & 1;    // 0..1
    const int grp  = lane >> 2;   // 0..7
    const int tig  = lane & 3;    // 0..3

    float acc[2][8][4];
    #pragma unroll
    for (int mt = 0; mt < 2; ++mt)
        #pragma unroll
        for (int nt = 0; nt < 8; ++nt)
            #pragma unroll
            for (int q = 0; q < 4; ++q)
                acc[mt][nt][q] = 0.f;

    const int rbase = wm * 32 + grp;
    const int cb    = wn * 64 + grp;

    for (int kc = 0; kc < CDIM / KC; ++kc) {
        const int kc0 = kc * KC;
        __syncthreads();
        // Load A chunk: 128 rows x 32 cols = 1024 float4 (4 per thread)
        #pragma unroll
        for (int i = 0; i < 4; ++i) {
            int li = tid + i * 256;
            int r  = li >> 3;
            int c  = (li & 7) << 2;
            float4 v = make_float4(0.f, 0.f, 0.f, 0.f);
            if (m0 + r < M)
                v = *reinterpret_cast<const float4*>(
                        X + (size_t)(m0 + r) * CDIM + kc0 + c);
            v.x = __uint_as_float(f2tf32(v.x));
            v.y = __uint_as_float(f2tf32(v.y));
            v.z = __uint_as_float(f2tf32(v.z));
            v.w = __uint_as_float(f2tf32(v.w));
            *reinterpret_cast<float4*>(As + r * AS_STRIDE + c) = v;
        }
        // Load B chunk: 32 rows x 128 cols = 1024 float4
        #pragma unroll
        for (int i = 0; i < 4; ++i) {
            int li = tid + i * 256;
            int r  = li >> 5;
            int c  = (li & 31) << 2;
            float4 v = *reinterpret_cast<const float4*>(
                           g_B + (size_t)(kc0 + r) * NCOLS + n0 + c);
            *reinterpret_cast<float4*>(Bs + r * BS_STRIDE + c) = v;
        }
        __syncthreads();

        #pragma unroll
        for (int ks = 0; ks < KC / 8; ++ks) {
            const int k0 = ks * 8;
            uint32_t a[2][4];
            #pragma unroll
            for (int mt = 0; mt < 2; ++mt) {
                int r0 = rbase + mt * 16;
                a[mt][0] = __float_as_uint(As[r0 * AS_STRIDE + k0 + tig]);
                a[mt][1] = __float_as_uint(As[(r0 + 8) * AS_STRIDE + k0 + tig]);
                a[mt][2] = __float_as_uint(As[r0 * AS_STRIDE + k0 + tig + 4]);
                a[mt][3] = __float_as_uint(As[(r0 + 8) * AS_STRIDE + k0 + tig + 4]);
            }
            #pragma unroll
            for (int nt = 0; nt < 8; ++nt) {
                uint32_t b0 = __float_as_uint(Bs[(k0 + tig) * BS_STRIDE + cb + nt * 8]);
                uint32_t b1 = __float_as_uint(Bs[(k0 + tig + 4) * BS_STRIDE + cb + nt * 8]);
                #pragma unroll
                for (int mt = 0; mt < 2; ++mt) {
                    asm volatile(
                        "mma.sync.aligned.m16n8k8.row.col.f32.tf32.tf32.f32 "
                        "{%0,%1,%2,%3}, {%4,%5,%6,%7}, {%8,%9}, {%0,%1,%2,%3};"
                        : "+f"(acc[mt][nt][0]), "+f"(acc[mt][nt][1]),
                          "+f"(acc[mt][nt][2]), "+f"(acc[mt][nt][3])
                        : "r"(a[mt][0]), "r"(a[mt][1]), "r"(a[mt][2]), "r"(a[mt][3]),
                          "r"(b0), "r"(b1));
                }
            }
        }
    }

    // Epilogue: float2 stores (32 B sectors fully used)
    #pragma unroll
    for (int mt = 0; mt < 2; ++mt) {
        int r0 = m0 + rbase + mt * 16;
        #pragma unroll
        for (int nt = 0; nt < 8; ++nt) {
            int cc = n0 + wn * 64 + nt * 8 + tig * 2;
            if (r0 < M) {
                float2 v = make_float2(acc[mt][nt][0], acc[mt][nt][1]);
                *reinterpret_cast<float2*>(g_Y + (size_t)r0 * NCOLS + cc) = v;
            }
            if (r0 + 8 < M) {
                float2 v = make_float2(acc[mt][nt][2], acc[mt][nt][3]);
                *reinterpret_cast<float2*>(g_Y + (size_t)(r0 + 8) * NCOLS + cc) = v;
            }
        }
    }
}

// ---------------------------------------------------------------------------
// Kernel 3: per edge e, out[e,:16] = tanh(Ysrc[src,t,:] + Ydst[dst,t,:])
// 4 threads per edge, float4 per thread; fully coalesced 64 B output.
// Index dtype (int32 vs int64) selected at runtime via g_idx64 (grid-uniform
// branch).
// ---------------------------------------------------------------------------
__global__ void edge_kernel(const void* __restrict__ ei,
                            const void* __restrict__ et,
                            float* __restrict__ out, int E) {
    int gid = blockIdx.x * blockDim.x + threadIdx.x;
    int e = gid >> 2;
    if (e >= E) return;
    int j = (gid & 3) << 2;

    int src, dst, t;
    if (g_idx64) {
        const long long* ei64 = (const long long*)ei;
        const long long* et64 = (const long long*)et;
        src = (int)ei64[e];
        dst = (int)ei64[(size_t)E + e];
        t   = (int)et64[e];
    } else {
        const int* ei32 = (const int*)ei;
        const int* et32 = (const int*)et;
        src = ei32[e];
        dst = ei32[(size_t)E + e];
        t   = et32[e];
    }

    const float4 a = *reinterpret_cast<const float4*>(
        g_Y + (size_t)src * NCOLS + t * 16 + j);
    const float4 b = *reinterpret_cast<const float4*>(
        g_Y + (size_t)dst * NCOLS + 192 + t * 16 + j);
    float4 r;
    r.x = tanhf(a.x + b.x);
    r.y = tanhf(a.y + b.y);
    r.z = tanhf(a.z + b.z);
    r.w = tanhf(a.w + b.w);
    *reinterpret_cast<float4*>(out + (size_t)e * 16 + j) = r;
}

// ---------------------------------------------------------------------------
extern "C" void kernel_launch(void* const* d_in, const int* in_sizes, int n_in,
                              void* d_out, int out_size) {
    const float* x  = (const float*)d_in[0];      // [N,128] f32
    const void*  ei = d_in[1];                    // [2,E] int32 or int64
    const void*  et = d_in[2];                    // [E]   int32 or int64
    const float* W  = (const float*)d_in[3];      // [12,256,16] f32

    const int N = in_sizes[0] / CDIM;
    const int E = in_sizes[2];

    // 0) Detect index dtype (deterministic, same result every call)
    detect_kernel<<<1, 256>>>((const int*)et);

    // 1) Weight rearrange + tf32 round (tiny)
    prep_B_kernel<<<(CDIM * NCOLS + 255) / 256, 256>>>(W);

    // 2) Dense node-side GEMM: Y = X @ B
    dim3 grid((N + 127) / 128, NCOLS / 128);
    gemm_kernel<<<grid, 256>>>(x, N);

    // 3) Edge gather + add + tanh
    int threads = E * 4;
    edge_kernel<<<(threads + 255) / 256, 256>>>(ei, et, (float*)d_out, E);
}

// round 6
// speedup vs baseline: 1.1661x; 1.1661x over previous
#include <cuda_runtime.h>
#include <cuda_fp16.h>
#include <cstdint>

// Problem constants (fixed by the dataset):
//   N = 50000 nodes, C = 128 channels, E = 400000 edges,
//   T = 12 edge types, P = 16 (4x4 restriction map)
// Y layout per node: [half(src=0/dst=1)][t][p]  -> 2*12*16 = 384 cols
#define NMAX   50000
#define CDIM   128
#define NCOLS  384

// Scratch (allocation-free rule: __device__ globals)
__device__ float  g_B[CDIM * NCOLS];                 // 196 KB, tf32-rounded weights
__device__ __half g_Yh[(size_t)NMAX * NCOLS];        // 38.4 MB, fp16 node partials
__device__ int    g_idx64;                           // 1 if indices are int64

__device__ __forceinline__ uint32_t f2tf32(float x) {
    uint32_t u;
    asm("cvt.rna.tf32.f32 %0, %1;" : "=r"(u) : "f"(x));
    return u;
}

__device__ __forceinline__ void cp_async16(float* smem_dst, const float* gsrc,
                                           int src_bytes) {
    uint32_t s = (uint32_t)__cvta_generic_to_shared(smem_dst);
    asm volatile("cp.async.ca.shared.global [%0], [%1], 16, %2;\n"
                 :: "r"(s), "l"(gsrc), "r"(src_bytes));
}
#define CP_COMMIT() asm volatile("cp.async.commit_group;\n" ::)
#define CP_WAIT(n)  asm volatile("cp.async.wait_group %0;\n" :: "n"(n))

// ---------------------------------------------------------------------------
// Kernel 0: detect index dtype. edge_types values are 0..11; if stored as
// int64 (little-endian), every odd int32 word is 0. False-int64 probability
// on genuine int32 data: (1/12)^256 ~ 0.
// ---------------------------------------------------------------------------
__global__ void detect_kernel(const int* __restrict__ et32) {
    int v = et32[2 * threadIdx.x + 1];
    int any_nonzero = __syncthreads_or(v != 0);
    if (threadIdx.x == 0) g_idx64 = any_nonzero ? 0 : 1;
}

// ---------------------------------------------------------------------------
// Kernel 1: rearrange W [T,2C,P] -> B [C, 384], col = half*192 + t*16 + p,
// pre-rounded to tf32 (rna).
// ---------------------------------------------------------------------------
__global__ void prep_B_kernel(const float* __restrict__ W) {
    int i = blockIdx.x * blockDim.x + threadIdx.x;
    if (i >= CDIM * NCOLS) return;
    int c    = i / NCOLS;
    int col  = i - c * NCOLS;
    int half = col / 192;
    int rem  = col - half * 192;
    int t    = rem >> 4;
    int p    = rem & 15;
    float w = W[((size_t)t * 256 + half * 128 + c) * 16 + p];
    g_B[i] = __uint_as_float(f2tf32(w));
}

// ---------------------------------------------------------------------------
// Kernel 2: Y[M,384] = tf32(X[M,128]) @ g_B[128,384], stored fp16.
// CTA tile 128x128, K chunked 4 x 32, cp.async DOUBLE-BUFFERED pipeline
// in DYNAMIC shared memory (71.7 KB > 48 KB static limit -> opt-in attr).
// 256 threads = 8 warps in 4(M) x 2(N); warp tile 32x64 via mma.m16n8k8.tf32.
// Smem strides: As 36 (banks 4*grp+tig, bijective), Bs 136 (8*tig+grp).
// ---------------------------------------------------------------------------
#define KC        32
#define NCHUNK    (CDIM / KC)
#define AS_STRIDE 36
#define BS_STRIDE 136
#define AS_ELEMS  (128 * AS_STRIDE)    // 4608 floats / buffer
#define BS_ELEMS  (KC * BS_STRIDE)     // 4352 floats / buffer
#define GEMM_SMEM_BYTES (2 * (AS_ELEMS + BS_ELEMS) * 4)   // 71680 B

__global__ void __launch_bounds__(256, 2)
gemm_kernel(const float* __restrict__ X, int M) {
    extern __shared__ float smem[];
    float* As[2] = { smem,              smem + AS_ELEMS };
    float* Bs[2] = { smem + 2 * AS_ELEMS, smem + 2 * AS_ELEMS + BS_ELEMS };

    const int m0  = blockIdx.x * 128;
    const int n0  = blockIdx.y * 128;
    const int tid = threadIdx.x;

    const int warp = tid >> 5;
    const int lane = tid & 31;
    const int wm   = warp >> 1;   // 0..3
    const int wn   = warp & 1;    // 0..1
    const int grp  = lane >> 2;   // 0..7
    const int tig  = lane & 3;    // 0..3

    // Per-thread load coordinates (constant across chunks)
    const int ar = tid >> 3;            // base A row (0..31), +32*i
    const int ac = (tid & 7) << 2;      // A col within chunk
    const int br = tid >> 5;            // base B row (0..7), +8*i
    const int bc = (tid & 31) << 2;     // B col within tile

    // Issue loads for a chunk into buffer buf
    auto load_chunk = [&](int kc, int buf) {
        const int kc0 = kc * KC;
        #pragma unroll
        for (int i = 0; i < 4; ++i) {
            int r = ar + i * 32;                       // 0..127
            int rc = (m0 + r < M) ? r : 0;             // clamp (valid address)
            int sz = (m0 + r < M) ? 16 : 0;            // zero-fill OOB rows
            cp_async16(&As[buf][r * AS_STRIDE + ac],
                       X + (size_t)(m0 + rc) * CDIM + kc0 + ac, sz);
        }
        #pragma unroll
        for (int i = 0; i < 4; ++i) {
            int r = br + i * 8;                        // 0..31
            cp_async16(&Bs[buf][r * BS_STRIDE + bc],
                       g_B + (size_t)(kc0 + r) * NCOLS + n0 + bc, 16);
        }
    };

    float acc[2][8][4];
    #pragma unroll
    for (int mt = 0; mt < 2; ++mt)
        #pragma unroll
        for (int nt = 0; nt < 8; ++nt)
            #pragma unroll
            for (int q = 0; q < 4; ++q)
                acc[mt][nt][q] = 0.f;

    const int rbase = wm * 32 + grp;
    const int cb    = wn * 64 + grp;

    load_chunk(0, 0);
    CP_COMMIT();

    #pragma unroll
    for (int kc = 0; kc < NCHUNK; ++kc) {
        const int buf = kc & 1;
        if (kc + 1 < NCHUNK) {
            load_chunk(kc + 1, (kc + 1) & 1);
            CP_COMMIT();
            CP_WAIT(1);            // chunk kc's group complete
        } else {
            CP_WAIT(0);
        }
        __syncthreads();

        #pragma unroll
        for (int ks = 0; ks < KC / 8; ++ks) {
            const int k0 = ks * 8;
            uint32_t a[2][4];
            #pragma unroll
            for (int mt = 0; mt < 2; ++mt) {
                int r0 = rbase + mt * 16;
                a[mt][0] = f2tf32(As[buf][r0 * AS_STRIDE + k0 + tig]);
                a[mt][1] = f2tf32(As[buf][(r0 + 8) * AS_STRIDE + k0 + tig]);
                a[mt][2] = f2tf32(As[buf][r0 * AS_STRIDE + k0 + tig + 4]);
                a[mt][3] = f2tf32(As[buf][(r0 + 8) * AS_STRIDE + k0 + tig + 4]);
            }
            #pragma unroll
            for (int nt = 0; nt < 8; ++nt) {
                uint32_t b0 = __float_as_uint(Bs[buf][(k0 + tig) * BS_STRIDE + cb + nt * 8]);
                uint32_t b1 = __float_as_uint(Bs[buf][(k0 + tig + 4) * BS_STRIDE + cb + nt * 8]);
                #pragma unroll
                for (int mt = 0; mt < 2; ++mt) {
                    asm volatile(
                        "mma.sync.aligned.m16n8k8.row.col.f32.tf32.tf32.f32 "
                        "{%0,%1,%2,%3}, {%4,%5,%6,%7}, {%8,%9}, {%0,%1,%2,%3};"
                        : "+f"(acc[mt][nt][0]), "+f"(acc[mt][nt][1]),
                          "+f"(acc[mt][nt][2]), "+f"(acc[mt][nt][3])
                        : "r"(a[mt][0]), "r"(a[mt][1]), "r"(a[mt][2]), "r"(a[mt][3]),
                          "r"(b0), "r"(b1));
                }
            }
        }
        __syncthreads();   // all warps done with buf before it is reloaded
    }

    // Epilogue: fp16 stores (half2, 4 B per thread per (mt,nt))
    #pragma unroll
    for (int mt = 0; mt < 2; ++mt) {
        int r0 = m0 + rbase + mt * 16;
        #pragma unroll
        for (int nt = 0; nt < 8; ++nt) {
            int cc = n0 + wn * 64 + nt * 8 + tig * 2;
            if (r0 < M) {
                __half2 h = __floats2half2_rn(acc[mt][nt][0], acc[mt][nt][1]);
                *reinterpret_cast<__half2*>(g_Yh + (size_t)r0 * NCOLS + cc) = h;
            }
            if (r0 + 8 < M) {
                __half2 h = __floats2half2_rn(acc[mt][nt][2], acc[mt][nt][3]);
                *reinterpret_cast<__half2*>(g_Yh + (size_t)(r0 + 8) * NCOLS + cc) = h;
            }
        }
    }
}

// ---------------------------------------------------------------------------
// Kernel 3: per edge e, out[e,:16] = tanh(Ysrc[src,t,:] + Ydst[dst,t,:])
// 2 threads per edge; each gathers 16 B (8 halfs) from each side, writes
// 2x float4. Y is fp16 (38.4 MB, fully L2-resident) -> gathers hit L2.
// ---------------------------------------------------------------------------
__global__ void edge_kernel(const void* __restrict__ ei,
                            const void* __restrict__ et,
                            float* __restrict__ out, int E) {
    int gid = blockIdx.x * blockDim.x + threadIdx.x;
    int e = gid >> 1;
    if (e >= E) return;
    int h = (gid & 1) << 3;   // 0 or 8 (element offset within the 16)

    int src, dst, t;
    if (g_idx64) {
        const long long* ei64 = (const long long*)ei;
        const long long* et64 = (const long long*)et;
        src = (int)ei64[e];
        dst = (int)ei64[(size_t)E + e];
        t   = (int)et64[e];
    } else {
        const int* ei32 = (const int*)ei;
        const int* et32 = (const int*)et;
        src = ei32[e];
        dst = ei32[(size_t)E + e];
        t   = et32[e];
    }

    const uint4 va = *reinterpret_cast<const uint4*>(
        g_Yh + (size_t)src * NCOLS + t * 16 + h);
    const uint4 vb = *reinterpret_cast<const uint4*>(
        g_Yh + (size_t)dst * NCOLS + 192 + t * 16 + h);
    const __half2* pa = reinterpret_cast<const __half2*>(&va);
    const __half2* pb = reinterpret_cast<const __half2*>(&vb);

    float r[8];
    #pragma unroll
    for (int i = 0; i < 4; ++i) {
        float2 fa = __half22float2(pa[i]);
        float2 fb = __half22float2(pb[i]);
        r[2 * i]     = tanhf(fa.x + fb.x);
        r[2 * i + 1] = tanhf(fa.y + fb.y);
    }
    float* o = out + (size_t)e * 16 + h;
    *reinterpret_cast<float4*>(o)     = make_float4(r[0], r[1], r[2], r[3]);
    *reinterpret_cast<float4*>(o + 4) = make_float4(r[4], r[5], r[6], r[7]);
}

// ---------------------------------------------------------------------------
extern "C" void kernel_launch(void* const* d_in, const int* in_sizes, int n_in,
                              void* d_out, int out_size) {
    const float* x  = (const float*)d_in[0];      // [N,128] f32
    const void*  ei = d_in[1];                    // [2,E] int32 or int64
    const void*  et = d_in[2];                    // [E]   int32 or int64
    const float* W  = (const float*)d_in[3];      // [12,256,16] f32

    const int N = in_sizes[0] / CDIM;
    const int E = in_sizes[2];

    // Opt-in to >48 KB dynamic smem. Not an allocation; not a stream op
    // (executes immediately, capture-legal). Called unconditionally —
    // deterministic, no static guards.
    cudaFuncSetAttribute(gemm_kernel,
                         cudaFuncAttributeMaxDynamicSharedMemorySize,
                         GEMM_SMEM_BYTES);

    // 0) Detect index dtype (deterministic, same result every call)
    detect_kernel<<<1, 256>>>((const int*)et);

    // 1) Weight rearrange + tf32 round (tiny)
    prep_B_kernel<<<(CDIM * NCOLS + 255) / 256, 256>>>(W);

    // 2) Dense node-side GEMM: Y = X @ B (fp16 output)
    dim3 grid((N + 127) / 128, NCOLS / 128);
    gemm_kernel<<<grid, 256, GEMM_SMEM_BYTES>>>(x, N);

    // 3) Edge gather + add + tanh
    int threads = E * 2;
    edge_kernel<<<(threads + 255) / 256, 256>>>(ei, et, (float*)d_out, E);
}

// round 7
// speedup vs baseline: 1.3956x; 1.1969x over previous
#include <cuda_runtime.h>
#include <cuda_fp16.h>
#include <cstdint>

// Problem constants (fixed by the dataset):
//   N = 50000 nodes, C = 128 channels, E = 400000 edges,
//   T = 12 edge types, P = 16 (4x4 restriction map)
// Y layout per node: [half(src=0/dst=1)][t][p]  -> 2*12*16 = 384 cols
#define NMAX   50000
#define CDIM   128
#define NCOLS  384

// Scratch (allocation-free rule: __device__ globals)
__device__ __half g_Bh[NCOLS * CDIM];                // 96 KB, fp16 W^T: [n][k]
__device__ __half g_Yh[(size_t)NMAX * NCOLS];        // 38.4 MB, fp16 node partials
__device__ int    g_idx64;                           // 1 if indices are int64

__device__ __forceinline__ void cp_async16(void* smem_dst, const void* gsrc) {
    uint32_t s = (uint32_t)__cvta_generic_to_shared(smem_dst);
    asm volatile("cp.async.ca.shared.global [%0], [%1], 16;\n"
                 :: "r"(s), "l"(gsrc));
}
#define CP_COMMIT() asm volatile("cp.async.commit_group;\n" ::)
#define CP_WAIT0()  asm volatile("cp.async.wait_group 0;\n" ::)

__device__ __forceinline__ float fast_tanh(float x) {
    float y;
    asm("tanh.approx.f32 %0, %1;" : "=f"(y) : "f"(x));
    return y;
}

// ---------------------------------------------------------------------------
// Kernel 1: prep. Blocks 0..191: rearrange W [T,2C,P] -> g_Bh [n=384][k=128]
// fp16, where n = half*192 + t*16 + p and k = channel c. Block 192: detect
// index dtype (edge_types values are 0..11; if int64, every odd int32 word
// is 0; false-int64 probability on real int32 data = (1/12)^256 ~ 0).
// ---------------------------------------------------------------------------
__global__ void prep_kernel(const float* __restrict__ W,
                            const int* __restrict__ et32) {
    if (blockIdx.x == 192) {
        int v = et32[2 * threadIdx.x + 1];
        int any_nonzero = __syncthreads_or(v != 0);
        if (threadIdx.x == 0) g_idx64 = any_nonzero ? 0 : 1;
        return;
    }
    int i = blockIdx.x * blockDim.x + threadIdx.x;   // 0 .. 49151
    int n = i >> 7;           // 0..383
    int k = i & 127;
    int half = n / 192;
    int rem  = n - half * 192;
    int t    = rem >> 4;
    int p    = rem & 15;
    float w = W[((size_t)t * 256 + half * 128 + k) * 16 + p];
    g_Bh[i] = __float2half_rn(w);
}

// ---------------------------------------------------------------------------
// Kernel 2: Y[M,384] = fp16(X[M,128]) @ Bh^T, fp32 accumulate, fp16 out.
// CTA tile 128(M) x 128(N), FULL K=128 resident in smem (single load phase,
// one __syncthreads, no K-chunk pipeline; load latency hidden by 2 CTA/SM
// across ~4 waves).
// 256 threads = 8 warps in 4(M) x 2(N); warp tile 32x64 via mma.m16n8k16.f16.
// Smem (fp16, stride 136 halves): As[128][136] + Bs[128][136] = 69.6 KB.
// Bank maps: half-pair LDS.32 at (row*136 + k0 + 2*tig)*2 bytes ->
// bank = (4*row + tig + 8*ks) mod 32, bijective over (grp,tig). Conflict-free.
// ---------------------------------------------------------------------------
#define SPAD      136
#define AS_ELEMS  (128 * SPAD)
#define GEMM_SMEM_BYTES (2 * AS_ELEMS * 2)   // 69632 B

__global__ void __launch_bounds__(256, 2)
gemm_kernel(const float* __restrict__ X, int M) {
    extern __shared__ __half smem[];
    __half* As = smem;              // [128][SPAD]  rows = m, cols = k
    __half* Bs = smem + AS_ELEMS;   // [128][SPAD]  rows = n_local, cols = k

    const int m0  = blockIdx.x * 128;
    const int n0  = blockIdx.y * 128;
    const int tid = threadIdx.x;

    // ---- B tile: straight fp16 row copy via cp.async (16 B chunks) ----
    #pragma unroll
    for (int i = 0; i < 8; ++i) {
        int li = tid + i * 256;          // 0..2047
        int r  = li >> 4;                // n_local 0..127
        int c  = (li & 15) << 3;         // k chunk start (8 halves)
        cp_async16(Bs + r * SPAD + c, g_Bh + (size_t)(n0 + r) * CDIM + c);
    }
    CP_COMMIT();

    // ---- A tile: LDG f32x4 -> cvt fp16 -> STS 8 B ----
    #pragma unroll
    for (int i = 0; i < 16; ++i) {
        int li = tid + i * 256;          // 0..4095
        int r  = li >> 5;                // m row 0..127
        int c  = (li & 31) << 2;         // k col (f32 granularity)
        float4 v = make_float4(0.f, 0.f, 0.f, 0.f);
        if (m0 + r < M)
            v = *reinterpret_cast<const float4*>(X + (size_t)(m0 + r) * CDIM + c);
        __half2 h0 = __floats2half2_rn(v.x, v.y);
        __half2 h1 = __floats2half2_rn(v.z, v.w);
        *reinterpret_cast<__half2*>(As + r * SPAD + c)     = h0;
        *reinterpret_cast<__half2*>(As + r * SPAD + c + 2) = h1;
    }
    CP_WAIT0();
    __syncthreads();

    const int warp = tid >> 5;
    const int lane = tid & 31;
    const int wm   = warp >> 1;   // 0..3
    const int wn   = warp & 1;    // 0..1
    const int grp  = lane >> 2;   // 0..7
    const int tig  = lane & 3;    // 0..3

    float acc[2][8][4];
    #pragma unroll
    for (int mt = 0; mt < 2; ++mt)
        #pragma unroll
        for (int nt = 0; nt < 8; ++nt)
            #pragma unroll
            for (int q = 0; q < 4; ++q)
                acc[mt][nt][q] = 0.f;

    const int rbase = wm * 32 + grp;          // A row base (within tile)
    const int nbase = wn * 64 + grp;          // B row base (n_local)

    #pragma unroll
    for (int ks = 0; ks < CDIM / 16; ++ks) {  // 8 k16 steps
        const int k0 = ks * 16;
        const int kk = k0 + 2 * tig;
        uint32_t a[2][4];
        #pragma unroll
        for (int mt = 0; mt < 2; ++mt) {
            int r0 = rbase + mt * 16;
            a[mt][0] = *reinterpret_cast<const uint32_t*>(As + r0 * SPAD + kk);
            a[mt][1] = *reinterpret_cast<const uint32_t*>(As + (r0 + 8) * SPAD + kk);
            a[mt][2] = *reinterpret_cast<const uint32_t*>(As + r0 * SPAD + kk + 8);
            a[mt][3] = *reinterpret_cast<const uint32_t*>(As + (r0 + 8) * SPAD + kk + 8);
        }
        #pragma unroll
        for (int nt = 0; nt < 8; ++nt) {
            const __half* bp = Bs + (nbase + nt * 8) * SPAD + kk;
            uint32_t b0 = *reinterpret_cast<const uint32_t*>(bp);
            uint32_t b1 = *reinterpret_cast<const uint32_t*>(bp + 8);
            #pragma unroll
            for (int mt = 0; mt < 2; ++mt) {
                asm volatile(
                    "mma.sync.aligned.m16n8k16.row.col.f32.f16.f16.f32 "
                    "{%0,%1,%2,%3}, {%4,%5,%6,%7}, {%8,%9}, {%0,%1,%2,%3};"
                    : "+f"(acc[mt][nt][0]), "+f"(acc[mt][nt][1]),
                      "+f"(acc[mt][nt][2]), "+f"(acc[mt][nt][3])
                    : "r"(a[mt][0]), "r"(a[mt][1]), "r"(a[mt][2]), "r"(a[mt][3]),
                      "r"(b0), "r"(b1));
            }
        }
    }

    // Epilogue: fp16 half2 stores
    #pragma unroll
    for (int mt = 0; mt < 2; ++mt) {
        int r0 = m0 + rbase + mt * 16;
        #pragma unroll
        for (int nt = 0; nt < 8; ++nt) {
            int cc = n0 + wn * 64 + nt * 8 + tig * 2;
            if (r0 < M) {
                __half2 h = __floats2half2_rn(acc[mt][nt][0], acc[mt][nt][1]);
                *reinterpret_cast<__half2*>(g_Yh + (size_t)r0 * NCOLS + cc) = h;
            }
            if (r0 + 8 < M) {
                __half2 h = __floats2half2_rn(acc[mt][nt][2], acc[mt][nt][3]);
                *reinterpret_cast<__half2*>(g_Yh + (size_t)(r0 + 8) * NCOLS + cc) = h;
            }
        }
    }
}

// ---------------------------------------------------------------------------
// Kernel 3: per edge e, out[e,:16] = tanh(Ysrc[src,t,:] + Ydst[dst,t,:])
// ONE thread per edge: 3 index loads + 4 independent 16 B gathers (high MLP),
// 16 MUFU tanh.approx, 4 float4 stores (full 64 B segment per thread).
// Y is fp16 (38.4 MB, L2-resident) -> gathers mostly hit L2.
// ---------------------------------------------------------------------------
__global__ void edge_kernel(const void* __restrict__ ei,
                            const void* __restrict__ et,
                            float* __restrict__ out, int E) {
    int e = blockIdx.x * blockDim.x + threadIdx.x;
    if (e >= E) return;

    int src, dst, t;
    if (g_idx64) {
        const long long* ei64 = (const long long*)ei;
        const long long* et64 = (const long long*)et;
        src = (int)ei64[e];
        dst = (int)ei64[(size_t)E + e];
        t   = (int)et64[e];
    } else {
        const int* ei32 = (const int*)ei;
        const int* et32 = (const int*)et;
        src = ei32[e];
        dst = ei32[(size_t)E + e];
        t   = et32[e];
    }

    const __half* pa = g_Yh + (size_t)src * NCOLS + t * 16;
    const __half* pb = g_Yh + (size_t)dst * NCOLS + 192 + t * 16;
    uint4 va0 = *reinterpret_cast<const uint4*>(pa);
    uint4 va1 = *reinterpret_cast<const uint4*>(pa + 8);
    uint4 vb0 = *reinterpret_cast<const uint4*>(pb);
    uint4 vb1 = *reinterpret_cast<const uint4*>(pb + 8);

    const __half2* a0 = reinterpret_cast<const __half2*>(&va0);
    const __half2* a1 = reinterpret_cast<const __half2*>(&va1);
    const __half2* b0 = reinterpret_cast<const __half2*>(&vb0);
    const __half2* b1 = reinterpret_cast<const __half2*>(&vb1);

    float r[16];
    #pragma unroll
    for (int i = 0; i < 4; ++i) {
        float2 fa = __half22float2(a0[i]);
        float2 fb = __half22float2(b0[i]);
        r[2 * i]     = fast_tanh(fa.x + fb.x);
        r[2 * i + 1] = fast_tanh(fa.y + fb.y);
        float2 ga = __half22float2(a1[i]);
        float2 gb = __half22float2(b1[i]);
        r[8 + 2 * i]     = fast_tanh(ga.x + gb.x);
        r[8 + 2 * i + 1] = fast_tanh(ga.y + gb.y);
    }
    float* o = out + (size_t)e * 16;
    *reinterpret_cast<float4*>(o)      = make_float4(r[0],  r[1],  r[2],  r[3]);
    *reinterpret_cast<float4*>(o + 4)  = make_float4(r[4],  r[5],  r[6],  r[7]);
    *reinterpret_cast<float4*>(o + 8)  = make_float4(r[8],  r[9],  r[10], r[11]);
    *reinterpret_cast<float4*>(o + 12) = make_float4(r[12], r[13], r[14], r[15]);
}

// ---------------------------------------------------------------------------
extern "C" void kernel_launch(void* const* d_in, const int* in_sizes, int n_in,
                              void* d_out, int out_size) {
    const float* x  = (const float*)d_in[0];      // [N,128] f32
    const void*  ei = d_in[1];                    // [2,E] int32 or int64
    const void*  et = d_in[2];                    // [E]   int32 or int64
    const float* W  = (const float*)d_in[3];      // [12,256,16] f32

    const int N = in_sizes[0] / CDIM;
    const int E = in_sizes[2];

    // Opt-in to >48 KB dynamic smem. Immediate host-side attr set: not an
    // allocation, not a stream op -> capture-legal. Unconditional ->
    // deterministic.
    cudaFuncSetAttribute(gemm_kernel,
                         cudaFuncAttributeMaxDynamicSharedMemorySize,
                         GEMM_SMEM_BYTES);

    // 1) Weight rearrange/transpose to fp16 + index-dtype detect (fused)
    prep_kernel<<<193, 256>>>(W, (const int*)et);

    // 2) Dense node-side GEMM: Y = X @ B (fp16 in/out, fp32 accumulate)
    dim3 grid((N + 127) / 128, NCOLS / 128);
    gemm_kernel<<<grid, 256, GEMM_SMEM_BYTES>>>(x, N);

    // 3) Edge gather + add + tanh
    edge_kernel<<<(E + 255) / 256, 256>>>(ei, et, (float*)d_out, E);
}